// round 16
// baseline (speedup 1.0000x reference)
#include <cuda_runtime.h>
#include <math.h>

// Problem constants
#define NB    2
#define NRR   16384
#define MMSK  64
#define AD    128
#define HIDN  512
#define TOK   16          // tokens per MLP block
#define NTHR  256
#define NTOK  (NB * NRR)  // 32768

typedef unsigned long long ull;

__device__ float g_x [NTOK * AD];   // LN1 output (residual for MLP)
__device__ float g_xn[NTOK * AD];   // LN2 output (MLP input)

__device__ __forceinline__ float warp_sum(float v) {
    #pragma unroll
    for (int s = 16; s; s >>= 1) v += __shfl_xor_sync(0xffffffffu, v, s);
    return v;
}
__device__ __forceinline__ float warp_max(float v) {
    #pragma unroll
    for (int s = 16; s; s >>= 1) v = fmaxf(v, __shfl_xor_sync(0xffffffffu, v, s));
    return v;
}

// packed f32x2 helpers (Blackwell FFMA2 — PTX-only path)
__device__ __forceinline__ ull pack2(float lo, float hi) {
    ull r; asm("mov.b64 %0, {%1, %2};" : "=l"(r) : "f"(lo), "f"(hi)); return r;
}
__device__ __forceinline__ void unpack2(ull v, float& lo, float& hi) {
    asm("mov.b64 {%0, %1}, %2;" : "=f"(lo), "=f"(hi) : "l"(v));
}
#define FFMA2(d, a, b, c) asm("fma.rn.f32x2 %0, %1, %2, %3;" : "=l"(d) : "l"(a), "l"(b), "l"(c))

__device__ __forceinline__ float gelu_f(float u) {
    return 0.5f * u * (1.0f + erff(u * 0.7071067811865476f));
}

// ===================== Kernel A: attention + LN1 + LN2, one token per block =====================
// Smem floats: Ks 8192 | Vs 8192 | qs 128 | mb 64 | att 256 | ra/rb/rc/rd 4x8 | avp 256
#define A_SMEM_FLOATS 17136
#define A_SMEM_BYTES  (A_SMEM_FLOATS * 4)

__global__ __launch_bounds__(NTHR, 3)
void attn_kernel(const float* __restrict__ Q,  const float* __restrict__ K,
                 const float* __restrict__ V,  const void*  __restrict__ maskp,
                 const float* __restrict__ g1, const float* __restrict__ be1,
                 const float* __restrict__ g2, const float* __restrict__ be2)
{
    extern __shared__ float sm[];
    float* Ks  = sm;              // swizzled K tile
    float* Vs  = sm + 8192;       // swizzled V tile
    float* qs  = sm + 16384;
    float* mb  = sm + 16512;
    float* att = sm + 16576;
    float* ra  = sm + 16832;
    float* rb  = sm + 16840;
    float* rc  = sm + 16848;
    float* rd  = sm + 16856;
    float* avp = sm + 16864;

    const int tid  = threadIdx.x;
    const int wid  = tid >> 5;
    const int lane = tid & 31;
    const size_t g = (size_t)blockIdx.x;
    const int n   = (int)(g % NRR);

    // K group first, V second -> V load overlaps logits+softmax
    {
        const float4* Kg = (const float4*)(K + g * (size_t)(MMSK * AD));
        const float4* Vg = (const float4*)(V + g * (size_t)(MMSK * AD));
        #pragma unroll
        for (int r = 0; r < 8; ++r) {
            int idx = tid + r * NTHR;          // float4 index in [0,2048)
            int m = idx >> 5, c = idx & 31;
            int u = (c + m) & 31;
            unsigned ka = (unsigned)__cvta_generic_to_shared(Ks + m * 128 + u * 4);
            asm volatile("cp.async.cg.shared.global [%0], [%1], 16;" :: "r"(ka), "l"(Kg + idx));
        }
        asm volatile("cp.async.commit_group;");        // group: K
        #pragma unroll
        for (int r = 0; r < 8; ++r) {
            int idx = tid + r * NTHR;
            int m = idx >> 5, c = idx & 31;
            int u = (c + m) & 31;
            unsigned va = (unsigned)__cvta_generic_to_shared(Vs + m * 128 + u * 4);
            asm volatile("cp.async.cg.shared.global [%0], [%1], 16;" :: "r"(va), "l"(Vg + idx));
        }
        asm volatile("cp.async.commit_group;");        // group: V
        if (tid < 32) ((float4*)qs)[tid] = ((const float4*)(Q + g * AD))[tid];

        // mask dtype detection (first 64 words — in-bounds either dtype)
        int ok = 1;
        if (tid < 64) {
            unsigned v = ((const unsigned*)maskp)[tid];
            if (!(v == 0u || v == 1u || v == 0x3F800000u)) ok = 0;
        }
        int wordmode = __syncthreads_and(ok);
        if (tid < MMSK) {
            bool masked;
            if (wordmode) masked = ((const unsigned*)maskp)[(size_t)n * MMSK + tid] != 0u;
            else          masked = ((const unsigned char*)maskp)[(size_t)n * MMSK + tid] != 0;
            mb[tid] = masked ? -INFINITY : 0.0f;
        }
        asm volatile("cp.async.wait_group 1;");        // K complete (V may be in flight)
        __syncthreads();                                                // BAR 1
    }

    // logits + softmax: warp w = head w (warps 0-3), lane owns m=lane and m=lane+32.
    if (wid < 4) {
        const int h = wid;
        const int m0 = lane, m1 = lane + 32;
        float acc0 = 0.f, acc1 = 0.f;
        #pragma unroll
        for (int j4 = 0; j4 < 8; ++j4) {
            int c = 8 * h + j4;
            float4 q4 = *(const float4*)(qs + c * 4);
            int u0 = (c + m0) & 31;
            float4 k0 = *(const float4*)(Ks + m0 * 128 + u0 * 4);
            acc0 = fmaf(k0.x, q4.x, acc0); acc0 = fmaf(k0.y, q4.y, acc0);
            acc0 = fmaf(k0.z, q4.z, acc0); acc0 = fmaf(k0.w, q4.w, acc0);
            int u1 = (c + m1) & 31;
            float4 k1 = *(const float4*)(Ks + m1 * 128 + u1 * 4);
            acc1 = fmaf(k1.x, q4.x, acc1); acc1 = fmaf(k1.y, q4.y, acc1);
            acc1 = fmaf(k1.z, q4.z, acc1); acc1 = fmaf(k1.w, q4.w, acc1);
        }
        float l0 = acc0 * 0.17677669529663689f + mb[m0];   // 1/sqrt(32)
        float l1 = acc1 * 0.17677669529663689f + mb[m1];
        float wm = warp_max(fmaxf(l0, l1));
        float p0 = __expf(l0 - wm), p1 = __expf(l1 - wm);
        float s  = warp_sum(p0 + p1);
        float inv = 1.0f / s;
        att[h * 64 + m0] = p0 * inv;
        att[h * 64 + m1] = p1 * inv;
    }
    asm volatile("cp.async.wait_group 0;");            // V complete
    __syncthreads();                                                    // BAR 2

    // AV: thread (o, half) sums 32 m; bank = (o + 4m) mod 32 -> conflict-free
    {
        int o = tid & 127, half = tid >> 7;
        int hh = o >> 5;
        const float* ah = att + hh * 64 + half * 32;
        float s = 0.f;
        #pragma unroll
        for (int i2 = 0; i2 < 32; ++i2) {
            int mm = half * 32 + i2;
            int u = (((o >> 2) + mm) & 31);
            s = fmaf(ah[i2], Vs[mm * 128 + u * 4 + (o & 3)], s);
        }
        avp[tid] = s;
    }
    __syncthreads();                                                    // BAR 3

    // residual + LN1 + LN2 via single-pass E[x^2]-E[x]^2
    const int o2 = tid & 127;
    float xv = 0.f;
    if (tid < 128) xv = qs[o2] + avp[o2] + avp[128 + o2];

    {
        float s1 = warp_sum((tid < 128) ? xv : 0.f);
        float s2 = warp_sum((tid < 128) ? xv * xv : 0.f);
        if (lane == 0 && wid < 4) { ra[wid] = s1; rb[wid] = s2; }
    }
    __syncthreads();                                                    // BAR 4
    float mu  = (ra[0] + ra[1] + ra[2] + ra[3]) * 0.0078125f;
    float ex2 = (rb[0] + rb[1] + rb[2] + rb[3]) * 0.0078125f;
    float var = ex2 - mu * mu;
    float x1 = 0.f;
    if (tid < 128)
        x1 = (xv - mu) * rsqrtf(var + 1e-5f) * __ldg(g1 + o2) + __ldg(be1 + o2);

    {
        float s1 = warp_sum((tid < 128) ? x1 : 0.f);
        float s2 = warp_sum((tid < 128) ? x1 * x1 : 0.f);
        if (lane == 0 && wid < 4) { rc[wid] = s1; rd[wid] = s2; }
    }
    __syncthreads();                                                    // BAR 5
    float mu2  = (rc[0] + rc[1] + rc[2] + rc[3]) * 0.0078125f;
    float ex22 = (rd[0] + rd[1] + rd[2] + rd[3]) * 0.0078125f;
    float var2 = ex22 - mu2 * mu2;
    if (tid < 128) {
        float xn2 = (x1 - mu2) * rsqrtf(var2 + 1e-5f) * __ldg(g2 + o2) + __ldg(be2 + o2);
        g_x [g * AD + o2] = x1;
        g_xn[g * AD + o2] = xn2;
    }
}

// ===================== Kernel B: MLP, 16 tokens/block, quad-blocked + lane-merged LDG =====================
// Smem floats: xs [16][128]=2048 | xnt/yp 2560 | hdnT [512][20]=10240  -> 14848 (59.4 KB)
// hdnT row map: row(j) = (j&3)*128 + (j>>2)
#define B_SMEM_FLOATS 14848
#define B_SMEM_BYTES  (B_SMEM_FLOATS * 4)

__global__ __launch_bounds__(NTHR, 3)
void mlp_kernel(const float* __restrict__ W1, const float* __restrict__ bb1,
                const float* __restrict__ W2, const float* __restrict__ bb2,
                float* __restrict__ out)
{
    extern __shared__ float sm[];
    float* xs   = sm;            // [16][128] residual x
    float* xnt  = sm + 2048;     // [128][20] LN2(x) transposed; reused as yp in GEMM2
    float* hdnT = sm + 4608;     // [512][20] via row map

    const int tid = threadIdx.x;
    const size_t gbase = (size_t)blockIdx.x * TOK;

    // load + transpose
    for (int i = tid; i < TOK * AD; i += NTHR) {
        int t = i >> 7, o = i & 127;
        xs[i] = g_x [(gbase + t) * AD + o];
        xnt[o * 20 + t] = g_xn[(gbase + t) * AD + o];
    }
    __syncthreads();

    // GEMM1: jq = tid>>1 (lane pairs share W1 quad -> LDG merges to 2 wf), th = tid&1.
    // Per W1 row: broadcast LDS.128 x2 + merged LDG.128 -> 16 FFMA2
    {
        const int jq = tid >> 1, th = tid & 1;
        const int toff = th * 8;
        const float4* w1v = (const float4*)W1 + jq;      // row o at w1v[o*128]
        ull A00=0,A01=0,A02=0,A03=0;   // j = 4jq+0, tokens as 4 f32x2
        ull A10=0,A11=0,A12=0,A13=0;   // +1
        ull A20=0,A21=0,A22=0,A23=0;   // +2
        ull A30=0,A31=0,A32=0,A33=0;   // +3
        for (int ob = 0; ob < 128; ob += 4) {
            float4 w[4];
            #pragma unroll
            for (int r = 0; r < 4; ++r) w[r] = __ldg(w1v + (ob + r) * 128);
            #pragma unroll
            for (int r = 0; r < 4; ++r) {
                const ulonglong2* xp = (const ulonglong2*)(xnt + (ob + r) * 20 + toff);
                ulonglong2 q0 = xp[0], q1 = xp[1];       // 8 tokens
                ull wp0 = pack2(w[r].x, w[r].x);
                ull wp1 = pack2(w[r].y, w[r].y);
                ull wp2 = pack2(w[r].z, w[r].z);
                ull wp3 = pack2(w[r].w, w[r].w);
                FFMA2(A00, q0.x, wp0, A00); FFMA2(A01, q0.y, wp0, A01);
                FFMA2(A02, q1.x, wp0, A02); FFMA2(A03, q1.y, wp0, A03);
                FFMA2(A10, q0.x, wp1, A10); FFMA2(A11, q0.y, wp1, A11);
                FFMA2(A12, q1.x, wp1, A12); FFMA2(A13, q1.y, wp1, A13);
                FFMA2(A20, q0.x, wp2, A20); FFMA2(A21, q0.y, wp2, A21);
                FFMA2(A22, q1.x, wp2, A22); FFMA2(A23, q1.y, wp2, A23);
                FFMA2(A30, q0.x, wp3, A30); FFMA2(A31, q0.y, wp3, A31);
                FFMA2(A32, q1.x, wp3, A32); FFMA2(A33, q1.y, wp3, A33);
            }
        }
        float4 b4 = __ldg((const float4*)bb1 + jq);
        ull Av[4][4] = {{A00,A01,A02,A03},{A10,A11,A12,A13},
                        {A20,A21,A22,A23},{A30,A31,A32,A33}};
        const float bk[4] = {b4.x, b4.y, b4.z, b4.w};
        #pragma unroll
        for (int k = 0; k < 4; ++k) {
            // row(4jq+k) = k*128 + jq
            float* hp = hdnT + (k * 128 + jq) * 20 + toff;
            #pragma unroll
            for (int q = 0; q < 4; ++q) {
                float lo, hi; unpack2(Av[k][q], lo, hi);
                float2 st; st.x = gelu_f(lo + bk[k]); st.y = gelu_f(hi + bk[k]);
                *(float2*)(hp + 2 * q) = st;
            }
        }
    }
    __syncthreads();

    // GEMM2: jh = tid>>7 (warp-uniform), oq = (tid>>2)&31 (8 lanes-groups merge W2 LDG
    // to 1 wf), tg = tid&3. Per j: single-row broadcast LDS.128 + merged LDG.128 -> 8 FFMA2
    {
        const int oq = (tid >> 2) & 31, tg = tid & 3, jh = tid >> 7;
        const int toff = tg * 4;
        const float4* w2v = (const float4*)W2 + oq;      // j at w2v[j*32]
        ull Y00=0,Y01=0, Y10=0,Y11=0, Y20=0,Y21=0, Y30=0,Y31=0;  // [o-k][token f32x2]
        const int j0 = jh * 256;
        for (int jb = 0; jb < 256; jb += 4) {
            float4 w[4];
            #pragma unroll
            for (int r = 0; r < 4; ++r) w[r] = __ldg(w2v + (j0 + jb + r) * 32);
            #pragma unroll
            for (int r = 0; r < 4; ++r) {
                int j = j0 + jb + r;
                int row = (j & 3) * 128 + (j >> 2);
                ulonglong2 hd = *(const ulonglong2*)(hdnT + row * 20 + toff); // 4 tokens
                ull wp0 = pack2(w[r].x, w[r].x);
                ull wp1 = pack2(w[r].y, w[r].y);
                ull wp2 = pack2(w[r].z, w[r].z);
                ull wp3 = pack2(w[r].w, w[r].w);
                FFMA2(Y00, hd.x, wp0, Y00); FFMA2(Y01, hd.y, wp0, Y01);
                FFMA2(Y10, hd.x, wp1, Y10); FFMA2(Y11, hd.y, wp1, Y11);
                FFMA2(Y20, hd.x, wp2, Y20); FFMA2(Y21, hd.y, wp2, Y21);
                FFMA2(Y30, hd.x, wp3, Y30); FFMA2(Y31, hd.y, wp3, Y31);
            }
        }
        float y[4][4];
        unpack2(Y00, y[0][0], y[0][1]); unpack2(Y01, y[0][2], y[0][3]);
        unpack2(Y10, y[1][0], y[1][1]); unpack2(Y11, y[1][2], y[1][3]);
        unpack2(Y20, y[2][0], y[2][1]); unpack2(Y21, y[2][2], y[2][3]);
        unpack2(Y30, y[3][0], y[3][1]); unpack2(Y31, y[3][2], y[3][3]);

        float* pp = xnt + (oq * 4 + tg) * 20;            // distinct banks across lanes
        __syncthreads();                                 // xnt reads (GEMM1) done; safe to overlay
        if (jh == 1) {
            #pragma unroll
            for (int k = 0; k < 4; ++k) {
                float4 st; st.x = y[k][0]; st.y = y[k][1]; st.z = y[k][2]; st.w = y[k][3];
                *(float4*)(pp + 4 * k) = st;
            }
        }
        __syncthreads();
        if (jh == 0) {
            float4 bv = __ldg((const float4*)bb2 + oq);
            #pragma unroll
            for (int k = 0; k < 4; ++k) {
                float4 pv = *(const float4*)(pp + 4 * k);
                y[k][0] += pv.x; y[k][1] += pv.y; y[k][2] += pv.z; y[k][3] += pv.w;
            }
            #pragma unroll
            for (int i = 0; i < 4; ++i) {
                int t = toff + i;
                float4 xr = *(const float4*)(xs + t * 128 + 4 * oq);
                float4 res;
                res.x = y[0][i] + xr.x + bv.x;
                res.y = y[1][i] + xr.y + bv.y;
                res.z = y[2][i] + xr.z + bv.z;
                res.w = y[3][i] + xr.w + bv.w;
                *(float4*)(out + (gbase + (size_t)t) * AD + 4 * oq) = res;
            }
        }
    }
}

extern "C" void kernel_launch(void* const* d_in, const int* in_sizes, int n_in,
                              void* d_out, int out_size)
{
    const float* Q   = (const float*)d_in[0];
    const float* K   = (const float*)d_in[1];
    const float* V   = (const float*)d_in[2];
    const void*  Mk  = d_in[3];
    const float* g1  = (const float*)d_in[4];
    const float* be1 = (const float*)d_in[5];
    const float* g2  = (const float*)d_in[6];
    const float* be2 = (const float*)d_in[7];
    const float* W1  = (const float*)d_in[8];
    const float* bb1 = (const float*)d_in[9];
    const float* W2  = (const float*)d_in[10];
    const float* bb2 = (const float*)d_in[11];
    float* out = (float*)d_out;

    cudaFuncSetAttribute(attn_kernel,
                         cudaFuncAttributeMaxDynamicSharedMemorySize, A_SMEM_BYTES);
    cudaFuncSetAttribute(mlp_kernel,
                         cudaFuncAttributeMaxDynamicSharedMemorySize, B_SMEM_BYTES);

    attn_kernel<<<NTOK, NTHR, A_SMEM_BYTES>>>(Q, K, V, Mk, g1, be1, g2, be2);

    mlp_kernel<<<NTOK / TOK, NTHR, B_SMEM_BYTES>>>(W1, bb1, W2, bb2, out);
    // 2 launches/call: odd profiled index -> ncu captures mlp_kernel.
}

// round 17
// speedup vs baseline: 1.0413x; 1.0413x over previous
#include <cuda_runtime.h>
#include <math.h>

// Problem constants
#define NB    2
#define NRR   16384
#define MMSK  64
#define AD    128
#define HIDN  512
#define TOKB  32          // tokens per MLP block
#define NTHR  256
#define NTOK  (NB * NRR)  // 32768

typedef unsigned long long ull;

__device__ float g_x [NTOK * AD];   // LN1 output (residual for MLP)
__device__ float g_xn[NTOK * AD];   // LN2 output (MLP input)

__device__ __forceinline__ float warp_sum(float v) {
    #pragma unroll
    for (int s = 16; s; s >>= 1) v += __shfl_xor_sync(0xffffffffu, v, s);
    return v;
}
__device__ __forceinline__ float warp_max(float v) {
    #pragma unroll
    for (int s = 16; s; s >>= 1) v = fmaxf(v, __shfl_xor_sync(0xffffffffu, v, s));
    return v;
}

// packed f32x2 helpers (Blackwell FFMA2 — PTX-only path)
__device__ __forceinline__ ull pack2(float lo, float hi) {
    ull r; asm("mov.b64 %0, {%1, %2};" : "=l"(r) : "f"(lo), "f"(hi)); return r;
}
__device__ __forceinline__ void unpack2(ull v, float& lo, float& hi) {
    asm("mov.b64 {%0, %1}, %2;" : "=f"(lo), "=f"(hi) : "l"(v));
}
#define FFMA2(d, a, b, c) asm("fma.rn.f32x2 %0, %1, %2, %3;" : "=l"(d) : "l"(a), "l"(b), "l"(c))

__device__ __forceinline__ float gelu_f(float u) {
    return 0.5f * u * (1.0f + erff(u * 0.7071067811865476f));
}

// ===================== Kernel A: attention + LN1 + LN2, one token per block =====================
// Smem floats: Ks 8192 | Vs 8192 | qs 128 | mb 64 | att 256 | ra/rb/rc/rd 4x8 | avp 256
#define A_SMEM_FLOATS 17136
#define A_SMEM_BYTES  (A_SMEM_FLOATS * 4)

__global__ __launch_bounds__(NTHR, 3)
void attn_kernel(const float* __restrict__ Q,  const float* __restrict__ K,
                 const float* __restrict__ V,  const void*  __restrict__ maskp,
                 const float* __restrict__ g1, const float* __restrict__ be1,
                 const float* __restrict__ g2, const float* __restrict__ be2)
{
    extern __shared__ float sm[];
    float* Ks  = sm;              // swizzled K tile
    float* Vs  = sm + 8192;       // swizzled V tile
    float* qs  = sm + 16384;
    float* mb  = sm + 16512;
    float* att = sm + 16576;
    float* ra  = sm + 16832;
    float* rb  = sm + 16840;
    float* rc  = sm + 16848;
    float* rd  = sm + 16856;
    float* avp = sm + 16864;

    const int tid  = threadIdx.x;
    const int wid  = tid >> 5;
    const int lane = tid & 31;
    const size_t g = (size_t)blockIdx.x;
    const int n   = (int)(g % NRR);

    // K group first, V second -> V load overlaps logits+softmax
    {
        const float4* Kg = (const float4*)(K + g * (size_t)(MMSK * AD));
        const float4* Vg = (const float4*)(V + g * (size_t)(MMSK * AD));
        #pragma unroll
        for (int r = 0; r < 8; ++r) {
            int idx = tid + r * NTHR;          // float4 index in [0,2048)
            int m = idx >> 5, c = idx & 31;
            int u = (c + m) & 31;
            unsigned ka = (unsigned)__cvta_generic_to_shared(Ks + m * 128 + u * 4);
            asm volatile("cp.async.cg.shared.global [%0], [%1], 16;" :: "r"(ka), "l"(Kg + idx));
        }
        asm volatile("cp.async.commit_group;");        // group: K
        #pragma unroll
        for (int r = 0; r < 8; ++r) {
            int idx = tid + r * NTHR;
            int m = idx >> 5, c = idx & 31;
            int u = (c + m) & 31;
            unsigned va = (unsigned)__cvta_generic_to_shared(Vs + m * 128 + u * 4);
            asm volatile("cp.async.cg.shared.global [%0], [%1], 16;" :: "r"(va), "l"(Vg + idx));
        }
        asm volatile("cp.async.commit_group;");        // group: V
        if (tid < 32) ((float4*)qs)[tid] = ((const float4*)(Q + g * AD))[tid];

        // mask dtype detection (first 64 words — in-bounds either dtype)
        int ok = 1;
        if (tid < 64) {
            unsigned v = ((const unsigned*)maskp)[tid];
            if (!(v == 0u || v == 1u || v == 0x3F800000u)) ok = 0;
        }
        int wordmode = __syncthreads_and(ok);
        if (tid < MMSK) {
            bool masked;
            if (wordmode) masked = ((const unsigned*)maskp)[(size_t)n * MMSK + tid] != 0u;
            else          masked = ((const unsigned char*)maskp)[(size_t)n * MMSK + tid] != 0;
            mb[tid] = masked ? -INFINITY : 0.0f;
        }
        asm volatile("cp.async.wait_group 1;");        // K complete (V may be in flight)
        __syncthreads();                                                // BAR 1
    }

    // logits + softmax: warp w = head w (warps 0-3), lane owns m=lane and m=lane+32.
    if (wid < 4) {
        const int h = wid;
        const int m0 = lane, m1 = lane + 32;
        float acc0 = 0.f, acc1 = 0.f;
        #pragma unroll
        for (int j4 = 0; j4 < 8; ++j4) {
            int c = 8 * h + j4;
            float4 q4 = *(const float4*)(qs + c * 4);
            int u0 = (c + m0) & 31;
            float4 k0 = *(const float4*)(Ks + m0 * 128 + u0 * 4);
            acc0 = fmaf(k0.x, q4.x, acc0); acc0 = fmaf(k0.y, q4.y, acc0);
            acc0 = fmaf(k0.z, q4.z, acc0); acc0 = fmaf(k0.w, q4.w, acc0);
            int u1 = (c + m1) & 31;
            float4 k1 = *(const float4*)(Ks + m1 * 128 + u1 * 4);
            acc1 = fmaf(k1.x, q4.x, acc1); acc1 = fmaf(k1.y, q4.y, acc1);
            acc1 = fmaf(k1.z, q4.z, acc1); acc1 = fmaf(k1.w, q4.w, acc1);
        }
        float l0 = acc0 * 0.17677669529663689f + mb[m0];   // 1/sqrt(32)
        float l1 = acc1 * 0.17677669529663689f + mb[m1];
        float wm = warp_max(fmaxf(l0, l1));
        float p0 = __expf(l0 - wm), p1 = __expf(l1 - wm);
        float s  = warp_sum(p0 + p1);
        float inv = 1.0f / s;
        att[h * 64 + m0] = p0 * inv;
        att[h * 64 + m1] = p1 * inv;
    }
    asm volatile("cp.async.wait_group 0;");            // V complete
    __syncthreads();                                                    // BAR 2

    // AV: thread (o, half) sums 32 m; bank = (o + 4m) mod 32 -> conflict-free
    {
        int o = tid & 127, half = tid >> 7;
        int hh = o >> 5;
        const float* ah = att + hh * 64 + half * 32;
        float s = 0.f;
        #pragma unroll
        for (int i2 = 0; i2 < 32; ++i2) {
            int mm = half * 32 + i2;
            int u = (((o >> 2) + mm) & 31);
            s = fmaf(ah[i2], Vs[mm * 128 + u * 4 + (o & 3)], s);
        }
        avp[tid] = s;
    }
    __syncthreads();                                                    // BAR 3

    // residual + LN1 + LN2 via single-pass E[x^2]-E[x]^2
    const int o2 = tid & 127;
    float xv = 0.f;
    if (tid < 128) xv = qs[o2] + avp[o2] + avp[128 + o2];

    {
        float s1 = warp_sum((tid < 128) ? xv : 0.f);
        float s2 = warp_sum((tid < 128) ? xv * xv : 0.f);
        if (lane == 0 && wid < 4) { ra[wid] = s1; rb[wid] = s2; }
    }
    __syncthreads();                                                    // BAR 4
    float mu  = (ra[0] + ra[1] + ra[2] + ra[3]) * 0.0078125f;
    float ex2 = (rb[0] + rb[1] + rb[2] + rb[3]) * 0.0078125f;
    float var = ex2 - mu * mu;
    float x1 = 0.f;
    if (tid < 128)
        x1 = (xv - mu) * rsqrtf(var + 1e-5f) * __ldg(g1 + o2) + __ldg(be1 + o2);

    {
        float s1 = warp_sum((tid < 128) ? x1 : 0.f);
        float s2 = warp_sum((tid < 128) ? x1 * x1 : 0.f);
        if (lane == 0 && wid < 4) { rc[wid] = s1; rd[wid] = s2; }
    }
    __syncthreads();                                                    // BAR 5
    float mu2  = (rc[0] + rc[1] + rc[2] + rc[3]) * 0.0078125f;
    float ex22 = (rd[0] + rd[1] + rd[2] + rd[3]) * 0.0078125f;
    float var2 = ex22 - mu2 * mu2;
    if (tid < 128) {
        float xn2 = (x1 - mu2) * rsqrtf(var2 + 1e-5f) * __ldg(g2 + o2) + __ldg(be2 + o2);
        g_x [g * AD + o2] = x1;
        g_xn[g * AD + o2] = xn2;
    }
}

// ===================== Kernel B: MLP, 32 tokens / 256 threads, ratio-4 blocking =====================
// Smem floats: xnt [128][36]=4608 | hdnT [512][36]=18432  -> 23040 floats = 92160 B
// hdnT row map: row(j) = (j&3)*128 + (j>>2).  GEMM2 partial slab reuses hdnT post-reads.
#define B_SMEM_FLOATS 23040
#define B_SMEM_BYTES  (B_SMEM_FLOATS * 4)

__global__ __launch_bounds__(NTHR, 2)
void mlp_kernel(const float* __restrict__ W1, const float* __restrict__ bb1,
                const float* __restrict__ W2, const float* __restrict__ bb2,
                float* __restrict__ out)
{
    extern __shared__ float sm[];
    float* xnt  = sm;            // [128][36] LN2(x) transposed
    float* hdnT = sm + 4608;     // [512][36] via row map

    const int tid = threadIdx.x;
    const size_t gbase = (size_t)blockIdx.x * TOKB;

    for (int i = tid; i < TOKB * AD; i += NTHR) {
        int t = i >> 7, o = i & 127;
        xnt[o * 36 + t] = g_xn[(gbase + t) * AD + o];
    }
    __syncthreads();

    // GEMM1: jq = tid&127 (j-quad), th = tid>>7 (16-token half, warp-uniform).
    // Per W1 row: 1 LDG.128 (4wf) + 4 broadcast LDS.128 (4wf) -> 32 FFMA2  (ratio 4)
    {
        const int jq = tid & 127, th = tid >> 7;
        const int toff = th * 16;
        const float4* w1v = (const float4*)W1 + jq;      // row o at w1v[o*128]
        ull A[4][8];
        #pragma unroll
        for (int k = 0; k < 4; ++k)
            #pragma unroll
            for (int q = 0; q < 8; ++q) A[k][q] = 0;
        for (int ob = 0; ob < 128; ob += 4) {
            float4 w[4];
            #pragma unroll
            for (int r = 0; r < 4; ++r) w[r] = __ldg(w1v + (ob + r) * 128);
            #pragma unroll
            for (int r = 0; r < 4; ++r) {
                const ulonglong2* xp = (const ulonglong2*)(xnt + (ob + r) * 36 + toff);
                ulonglong2 q0 = xp[0], q1 = xp[1], q2 = xp[2], q3 = xp[3]; // 16 tokens
                ull wp[4];
                wp[0] = pack2(w[r].x, w[r].x);
                wp[1] = pack2(w[r].y, w[r].y);
                wp[2] = pack2(w[r].z, w[r].z);
                wp[3] = pack2(w[r].w, w[r].w);
                #pragma unroll
                for (int k = 0; k < 4; ++k) {
                    FFMA2(A[k][0], q0.x, wp[k], A[k][0]);
                    FFMA2(A[k][1], q0.y, wp[k], A[k][1]);
                    FFMA2(A[k][2], q1.x, wp[k], A[k][2]);
                    FFMA2(A[k][3], q1.y, wp[k], A[k][3]);
                    FFMA2(A[k][4], q2.x, wp[k], A[k][4]);
                    FFMA2(A[k][5], q2.y, wp[k], A[k][5]);
                    FFMA2(A[k][6], q3.x, wp[k], A[k][6]);
                    FFMA2(A[k][7], q3.y, wp[k], A[k][7]);
                }
            }
        }
        float4 b4 = __ldg((const float4*)bb1 + jq);
        const float bk[4] = {b4.x, b4.y, b4.z, b4.w};
        #pragma unroll
        for (int k = 0; k < 4; ++k) {
            // row(4jq+k) = k*128 + jq
            float* hp = hdnT + (k * 128 + jq) * 36 + toff;
            #pragma unroll
            for (int q = 0; q < 8; ++q) {
                float lo, hi; unpack2(A[k][q], lo, hi);
                float2 st; st.x = gelu_f(lo + bk[k]); st.y = gelu_f(hi + bk[k]);
                *(float2*)(hp + 2 * q) = st;
            }
        }
    }
    __syncthreads();

    // GEMM2: oq = tid&31 (o-quad), tg = (tid>>5)&1 (16-token half), jh = tid>>6 (j-slice of 128).
    // Per j: 1 LDG.128 (4wf) + 4 broadcast LDS.128 (4wf) -> 32 FFMA2  (ratio 4)
    {
        const int oq = tid & 31, tg = (tid >> 5) & 1, jh = tid >> 6;   // jh 0..3
        const int toff = tg * 16;
        const float4* w2v = (const float4*)W2 + oq;       // j at w2v[j*32]
        ull Y[4][8];
        #pragma unroll
        for (int k = 0; k < 4; ++k)
            #pragma unroll
            for (int q = 0; q < 8; ++q) Y[k][q] = 0;
        const int j0 = jh * 128;
        for (int jb = 0; jb < 128; jb += 4) {
            float4 w[4];
            #pragma unroll
            for (int r = 0; r < 4; ++r) w[r] = __ldg(w2v + (j0 + jb + r) * 32);
            #pragma unroll
            for (int r = 0; r < 4; ++r) {
                int j = j0 + jb + r;
                int row = (j & 3) * 128 + (j >> 2);
                const ulonglong2* hp = (const ulonglong2*)(hdnT + row * 36 + toff);
                ulonglong2 h0 = hp[0], h1 = hp[1], h2 = hp[2], h3 = hp[3]; // 16 tokens
                ull wp[4];
                wp[0] = pack2(w[r].x, w[r].x);
                wp[1] = pack2(w[r].y, w[r].y);
                wp[2] = pack2(w[r].z, w[r].z);
                wp[3] = pack2(w[r].w, w[r].w);
                #pragma unroll
                for (int k = 0; k < 4; ++k) {
                    FFMA2(Y[k][0], h0.x, wp[k], Y[k][0]);
                    FFMA2(Y[k][1], h0.y, wp[k], Y[k][1]);
                    FFMA2(Y[k][2], h1.x, wp[k], Y[k][2]);
                    FFMA2(Y[k][3], h1.y, wp[k], Y[k][3]);
                    FFMA2(Y[k][4], h2.x, wp[k], Y[k][4]);
                    FFMA2(Y[k][5], h2.y, wp[k], Y[k][5]);
                    FFMA2(Y[k][6], h3.x, wp[k], Y[k][6]);
                    FFMA2(Y[k][7], h3.y, wp[k], Y[k][7]);
                }
            }
        }
        float y[4][16];
        #pragma unroll
        for (int k = 0; k < 4; ++k)
            #pragma unroll
            for (int q = 0; q < 8; ++q)
                unpack2(Y[k][q], y[k][2 * q], y[k][2 * q + 1]);

        // combine partials across jh groups via hdnT reuse (all reads of hdnT are done)
        __syncthreads();
        // slot per (jh-1, tg, oq): 68-float stride (16B-aligned), layout k*16 + i
        if (jh != 0) {
            float* base = hdnT + ((jh - 1) * 64 + tg * 32 + oq) * 68;
            #pragma unroll
            for (int k = 0; k < 4; ++k)
                #pragma unroll
                for (int q = 0; q < 4; ++q) {
                    float4 st;
                    st.x = y[k][4 * q    ]; st.y = y[k][4 * q + 1];
                    st.z = y[k][4 * q + 2]; st.w = y[k][4 * q + 3];
                    *(float4*)(base + k * 16 + 4 * q) = st;
                }
        }
        __syncthreads();
        if (jh == 0) {
            #pragma unroll
            for (int pp = 0; pp < 3; ++pp) {
                const float* base = hdnT + (pp * 64 + tg * 32 + oq) * 68;
                #pragma unroll
                for (int k = 0; k < 4; ++k)
                    #pragma unroll
                    for (int q = 0; q < 4; ++q) {
                        float4 pv = *(const float4*)(base + k * 16 + 4 * q);
                        y[k][4 * q    ] += pv.x; y[k][4 * q + 1] += pv.y;
                        y[k][4 * q + 2] += pv.z; y[k][4 * q + 3] += pv.w;
                    }
            }
            float4 bv = __ldg((const float4*)bb2 + oq);
            #pragma unroll
            for (int i = 0; i < 16; ++i) {
                int t = toff + i;
                float4 xr = __ldg((const float4*)(g_x + (gbase + (size_t)t) * AD) + oq);
                float4 res;
                res.x = y[0][i] + xr.x + bv.x;
                res.y = y[1][i] + xr.y + bv.y;
                res.z = y[2][i] + xr.z + bv.z;
                res.w = y[3][i] + xr.w + bv.w;
                *(float4*)(out + (gbase + (size_t)t) * AD + 4 * oq) = res;
            }
        }
    }
}

extern "C" void kernel_launch(void* const* d_in, const int* in_sizes, int n_in,
                              void* d_out, int out_size)
{
    const float* Q   = (const float*)d_in[0];
    const float* K   = (const float*)d_in[1];
    const float* V   = (const float*)d_in[2];
    const void*  Mk  = d_in[3];
    const float* g1  = (const float*)d_in[4];
    const float* be1 = (const float*)d_in[5];
    const float* g2  = (const float*)d_in[6];
    const float* be2 = (const float*)d_in[7];
    const float* W1  = (const float*)d_in[8];
    const float* bb1 = (const float*)d_in[9];
    const float* W2  = (const float*)d_in[10];
    const float* bb2 = (const float*)d_in[11];
    float* out = (float*)d_out;

    cudaFuncSetAttribute(attn_kernel,
                         cudaFuncAttributeMaxDynamicSharedMemorySize, A_SMEM_BYTES);
    cudaFuncSetAttribute(mlp_kernel,
                         cudaFuncAttributeMaxDynamicSharedMemorySize, B_SMEM_BYTES);

    attn_kernel<<<NTOK, NTHR, A_SMEM_BYTES>>>(Q, K, V, Mk, g1, be1, g2, be2);

    mlp_kernel<<<NTOK / TOKB, NTHR, B_SMEM_BYTES>>>(W1, bb1, W2, bb2, out);
    // 2 launches/call: odd profiled index -> ncu captures mlp_kernel.
}